// round 8
// baseline (speedup 1.0000x reference)
#include <cuda_runtime.h>
#include <cuda_bf16.h>

// 3x3 stride-2 VALID average pooling, fp32.
// x: (8, 64, 512, 512) -> out: (8, 64, 255, 255)

#define IN_H 512
#define IN_W 512
#define OUT_H 255
#define OUT_W 255
#define ROWS_PER_BLOCK 8                    // output rows per CTA
#define IN_ROWS (2 * ROWS_PER_BLOCK + 1)    // 17 input rows staged
#define NTHREADS 256
#define STAGE_ELEMS (IN_ROWS * (IN_W / 4))  // 17 * 128 = 2176 float4 elements

__global__ __launch_bounds__(NTHREADS)
void KeyedAvgpool2d_2413771620972_kernel(const float* __restrict__ x,
                                         float* __restrict__ out)
{
    __shared__ float s[IN_ROWS][IN_W];

    const int rb  = blockIdx.x;   // row-block within plane (fast axis -> L2 reuse of boundary row)
    const int nc  = blockIdx.y;   // plane index (N*C)
    const int tid = threadIdx.x;

    const int ih0 = rb * (2 * ROWS_PER_BLOCK);   // first input row this CTA needs

    // ---- Stage IN_ROWS x IN_W floats into smem with float4 loads ----
    // 2176 float4 / 256 threads = 8.5 iterations; explicit unroll so ptxas
    // front-batches the LDG.128s (high MLP before the smem stores).
    const float4* __restrict__ x4 =
        reinterpret_cast<const float4*>(x + (size_t)nc * IN_H * IN_W);

    #pragma unroll
    for (int it = 0; it < 9; it++) {
        const int i = tid + it * NTHREADS;
        if (i < STAGE_ELEMS) {
            const int r  = i >> 7;        // i / 128
            const int c4 = i & 127;       // i % 128
            const int ih = ih0 + r;
            if (ih < IN_H) {
                float4 v = x4[(size_t)ih * (IN_W / 4) + c4];
                *reinterpret_cast<float4*>(&s[r][c4 * 4]) = v;
            }
        }
    }
    __syncthreads();

    // ---- Compute: each thread owns one output column ----
    if (tid < OUT_W) {
        const int iw = 2 * tid;
        const float inv9 = 1.0f / 9.0f;
        float* __restrict__ op =
            out + (size_t)nc * OUT_H * OUT_W + (size_t)(rb * ROWS_PER_BLOCK) * OUT_W + tid;

        // Horizontal triple-sums per staged row; each even row's sum is
        // reused by the two vertically-adjacent output rows.
        float hs[IN_ROWS];
        #pragma unroll
        for (int r = 0; r < IN_ROWS; r++) {
            hs[r] = s[r][iw] + s[r][iw + 1] + s[r][iw + 2];
        }

        #pragma unroll
        for (int r = 0; r < ROWS_PER_BLOCK; r++) {
            const int oh = rb * ROWS_PER_BLOCK + r;
            if (oh < OUT_H) {
                float sum = hs[2 * r] + hs[2 * r + 1] + hs[2 * r + 2];
                op[(size_t)r * OUT_W] = sum * inv9;
            }
        }
    }
}

extern "C" void kernel_launch(void* const* d_in, const int* in_sizes, int n_in,
                              void* d_out, int out_size)
{
    const float* x = (const float*)d_in[0];
    float* out = (float*)d_out;

    dim3 grid((OUT_H + ROWS_PER_BLOCK - 1) / ROWS_PER_BLOCK,
              in_sizes[0] / (IN_H * IN_W));   // 32 x 512
    KeyedAvgpool2d_2413771620972_kernel<<<grid, NTHREADS>>>(x, out);
}